// round 13
// baseline (speedup 1.0000x reference)
#include <cuda_runtime.h>
#include <cuda_fp16.h>
#include <cstdint>

#define N 4096
#define D 1024
#define EPSV 1e-8f
#define MARGIN 0.1f

#define BM 128
#define BN 128
#define BK 64          // 64 fp16 = 128 B per smem row (SW128 atom)
#define NKC (D / BK)   // 16 k-chunks
#define NT  ((N / BM) * (N / BN))    // 1024 tiles
#define NBLK 444                      // 148 SMs x 3 CTAs: one resident wave

// ---------------- device globals (scratch) -----------------------------------
__device__ float  g_rnw[N];
__device__ float  g_rno[N];
__device__ float  g_d[N];
__device__ double g_acc = 0.0;
__device__ unsigned int g_ticket = 0;
__device__ unsigned int g_tile = NBLK;   // dynamic tile ticket (first NBLK taken by blockIdx)
__device__ __half g_Wh[(size_t)N * D];
__device__ __half g_Oh[(size_t)N * D];

// ---------------- helpers ----------------------------------------------------
__device__ __forceinline__ uint32_t smem_u32(const void* p) {
    uint32_t a;
    asm("{ .reg .u64 t; cvta.to.shared.u64 t, %1; cvt.u32.u64 %0, t; }" : "=r"(a) : "l"(p));
    return a;
}
__device__ __forceinline__ float warp_sum(float v) {
    #pragma unroll
    for (int off = 16; off > 0; off >>= 1) v += __shfl_down_sync(0xFFFFFFFFu, v, off);
    return v;
}
__device__ __forceinline__ uint32_t swz128(uint32_t off) { return off ^ ((off >> 3) & 0x70); }

__device__ __forceinline__ void cp_async16(uint32_t saddr, const void* gaddr) {
    asm volatile("cp.async.cg.shared.global [%0], [%1], 16;" :: "r"(saddr), "l"(gaddr));
}
#define CP_COMMIT() asm volatile("cp.async.commit_group;" ::: "memory")
#define CP_WAIT0()  asm volatile("cp.async.wait_group 0;" ::: "memory")

__device__ __forceinline__ void ldsm_x4(uint32_t* r, uint32_t addr) {
    asm volatile("ldmatrix.sync.aligned.m8n8.x4.shared.b16 {%0,%1,%2,%3}, [%4];"
                 : "=r"(r[0]), "=r"(r[1]), "=r"(r[2]), "=r"(r[3]) : "r"(addr));
}
__device__ __forceinline__ void mma_f16acc(uint32_t* c, const uint32_t* a, const uint32_t* b) {
    asm volatile(
        "mma.sync.aligned.m16n8k16.row.col.f16.f16.f16.f16 "
        "{%0,%1}, {%2,%3,%4,%5}, {%6,%7}, {%0,%1};"
        : "+r"(c[0]), "+r"(c[1])
        : "r"(a[0]), "r"(a[1]), "r"(a[2]), "r"(a[3]), "r"(b[0]), "r"(b[1]));
}

// ---------------- kernel 1: row stats + fp16 convert (4 rows/block, MLP 8) ---
__global__ void row_stats_kernel(const float* __restrict__ W, const float* __restrict__ O) {
    const int t = threadIdx.x;
    const int r = t >> 6;
    const int c = t & 63;
    const int row = blockIdx.x * 4 + r;

    const float4* W4 = reinterpret_cast<const float4*>(W + (size_t)row * D);
    const float4* O4 = reinterpret_cast<const float4*>(O + (size_t)row * D);

    float4 a[4], b[4];
    #pragma unroll
    for (int i = 0; i < 4; ++i) a[i] = W4[c + 64 * i];
    #pragma unroll
    for (int i = 0; i < 4; ++i) b[i] = O4[c + 64 * i];

    uint2* Wp = reinterpret_cast<uint2*>(g_Wh + (size_t)row * D);
    uint2* Op = reinterpret_cast<uint2*>(g_Oh + (size_t)row * D);
    #pragma unroll
    for (int i = 0; i < 4; ++i) {
        __half2 lo = __float22half2_rn(make_float2(a[i].x, a[i].y));
        __half2 hi = __float22half2_rn(make_float2(a[i].z, a[i].w));
        Wp[c + 64 * i] = make_uint2(*(uint32_t*)&lo, *(uint32_t*)&hi);
    }
    #pragma unroll
    for (int i = 0; i < 4; ++i) {
        __half2 lo = __float22half2_rn(make_float2(b[i].x, b[i].y));
        __half2 hi = __float22half2_rn(make_float2(b[i].z, b[i].w));
        Op[c + 64 * i] = make_uint2(*(uint32_t*)&lo, *(uint32_t*)&hi);
    }

    float ww = 0.f, oo = 0.f, wo = 0.f;
    #pragma unroll
    for (int i = 0; i < 4; ++i) {
        ww += a[i].x*a[i].x + a[i].y*a[i].y + a[i].z*a[i].z + a[i].w*a[i].w;
        oo += b[i].x*b[i].x + b[i].y*b[i].y + b[i].z*b[i].z + b[i].w*b[i].w;
        wo += a[i].x*b[i].x + a[i].y*b[i].y + a[i].z*b[i].z + a[i].w*b[i].w;
    }
    ww = warp_sum(ww); oo = warp_sum(oo); wo = warp_sum(wo);

    __shared__ float sw[8], so[8], sd[8];
    const int lane = t & 31, wid = t >> 5;
    if (lane == 0) { sw[wid] = ww; so[wid] = oo; sd[wid] = wo; }
    __syncthreads();
    if (c == 0) {
        float vw = sw[2*r] + sw[2*r+1];
        float vo = so[2*r] + so[2*r+1];
        float vd = sd[2*r] + sd[2*r+1];
        float nw = sqrtf(vw), no = sqrtf(vo);
        float prod = fmaxf(nw * no, EPSV);
        g_rnw[row] = 1.0f / nw;
        g_rno[row] = 1.0f / no;
        g_d[row]   = vd / prod;
    }
}

// ---------------- kernel 2: persistent fp16-acc mma GEMM ---------------------
// per CTA smem: 2x(A 16KB) + 2x(B 16KB) = 64 KB -> 3 CTAs/SM
#define SM_A0    0
#define SM_A1    (SM_A0 + BM * 128)
#define SM_B0    (SM_A1 + BM * 128)
#define SM_B1    (SM_B0 + BN * 128)
#define SM_TOTAL (SM_B1 + BN * 128)

__global__ __launch_bounds__(256, 3)
void gemm_loss_mma(float* __restrict__ out) {
    extern __shared__ char smem[];
    __shared__ unsigned s_next;
    __shared__ float red[8];
    const uint32_t sbase = smem_u32(smem);
    const int tid  = threadIdx.x;
    const int wid  = tid >> 5;
    const int lane = tid & 31;
    const int warp_m = wid >> 2;       // 0..1 (64 rows each)
    const int warp_n = wid & 3;        // 0..3 (32 cols each)

    const int lrow = tid >> 3;         // 0..31 (+32*i)
    const int lcol = tid & 7;

    const int a_row = warp_m * 64 + ((lane >> 3) & 1) * 8 + (lane & 7);
    const int a_cb  = (lane >> 4) * 16;
    const int b_row = warp_n * 32 + ((lane >> 4) & 1) * 8 + (lane & 7);
    const int b_cb  = ((lane >> 3) & 1) * 16;

    const int qrow = lane >> 2;
    const int qcol = (lane & 3) * 2;

    uint32_t acc[4][4][2];
    #pragma unroll
    for (int f = 0; f < 4; ++f)
        #pragma unroll
        for (int g = 0; g < 4; ++g)
            acc[f][g][0] = acc[f][g][1] = 0u;

    unsigned cur = blockIdx.x;          // first tile; later ones via ticket
    const __half* Wt = g_Wh + (size_t)((cur >> 5) * BM) * D;
    const __half* Ot = g_Oh + (size_t)((cur & 31) * BN) * D;

    // prime: chunk 0 of first tile into buffer 0
    #pragma unroll
    for (int i = 0; i < 4; ++i) {
        int row = lrow + i * 32;
        cp_async16(sbase + SM_A0 + swz128(row * 128 + lcol * 16),
                   Wt + (size_t)row * D + lcol * 8);
        cp_async16(sbase + SM_B0 + swz128(row * 128 + lcol * 16),
                   Ot + (size_t)row * D + lcol * 8);
    }
    CP_COMMIT();

    int par = 0;                        // buffer holding the chunk to compute
    float lsum = 0.f;

    while (cur < NT) {
        const int bi = cur >> 5;
        const int bj = cur & 31;
        const __half* Wn = Wt;          // next-tile pointers (set at kc==15)
        const __half* On = Ot;
        unsigned nxt = NT;

        #pragma unroll 1
        for (int kc = 0; kc < NKC; ++kc) {
            CP_WAIT0();
            __syncthreads();           // publishes s_next written at kc==14

            if (kc == 14 && tid == 0)
                s_next = atomicAdd(&g_tile, 1u);

            const uint32_t sa = sbase + (par ? SM_A0 : SM_A1);   // fill other buffer
            const uint32_t sb = sbase + (par ? SM_B0 : SM_B1);
            if (kc < 15) {
                const int kt = (kc + 1) * BK;
                #pragma unroll
                for (int i = 0; i < 4; ++i) {
                    int row = lrow + i * 32;
                    cp_async16(sa + swz128(row * 128 + lcol * 16),
                               Wt + (size_t)row * D + kt + lcol * 8);
                    cp_async16(sb + swz128(row * 128 + lcol * 16),
                               Ot + (size_t)row * D + kt + lcol * 8);
                }
                CP_COMMIT();
            } else {
                nxt = s_next;
                if (nxt < NT) {
                    Wn = g_Wh + (size_t)((nxt >> 5) * BM) * D;
                    On = g_Oh + (size_t)((nxt & 31) * BN) * D;
                    #pragma unroll
                    for (int i = 0; i < 4; ++i) {
                        int row = lrow + i * 32;
                        cp_async16(sa + swz128(row * 128 + lcol * 16),
                                   Wn + (size_t)row * D + lcol * 8);
                        cp_async16(sb + swz128(row * 128 + lcol * 16),
                                   On + (size_t)row * D + lcol * 8);
                    }
                    CP_COMMIT();
                }
            }

            const uint32_t abuf = sbase + (par ? SM_A1 : SM_A0);
            const uint32_t bbuf = sbase + (par ? SM_B1 : SM_B0);
            #pragma unroll
            for (int ks = 0; ks < 4; ++ks) {
                uint32_t areg[4][4];
                uint32_t breg[2][4];
                #pragma unroll
                for (int f = 0; f < 4; ++f)
                    ldsm_x4(areg[f], abuf + swz128((a_row + f * 16) * 128 + a_cb + ks * 32));
                #pragma unroll
                for (int n2 = 0; n2 < 2; ++n2)
                    ldsm_x4(breg[n2], bbuf + swz128((b_row + n2 * 16) * 128 + b_cb + ks * 32));
                #pragma unroll
                for (int f = 0; f < 4; ++f)
                    #pragma unroll
                    for (int g = 0; g < 4; ++g)
                        mma_f16acc(acc[f][g], areg[f], &breg[g >> 1][(g & 1) * 2]);
            }
            par ^= 1;
        }

        // ---- per-tile epilogue: stats straight from L2; accumulate lsum ------
        #pragma unroll
        for (int g = 0; g < 4; ++g) {
            #pragma unroll
            for (int e = 0; e < 2; ++e) {
                const int cl = warp_n * 32 + g * 8 + qcol + e;
                const float rno_c = g_rno[bj * BN + cl];
                const int jg = bj * BN + cl;
                #pragma unroll
                for (int f = 0; f < 4; ++f) {
                    #pragma unroll
                    for (int h = 0; h < 2; ++h) {
                        const int rl = warp_m * 64 + f * 16 + qrow + h * 8;
                        const int rg = bi * BM + rl;
                        const float rnw_r = g_rnw[rg];
                        const float d_r   = g_d[rg];
                        const __half2 hv = *reinterpret_cast<__half2*>(&acc[f][g][h]);
                        const float sv = (e ? __high2float(hv) : __low2float(hv));
                        const float S = sv * rnw_r * rno_c;
                        lsum += (rg == jg) ? (1.0f - d_r) : fmaxf(MARGIN - S + d_r, 0.0f);
                    }
                }
            }
        }
        // zero accumulators for next tile
        #pragma unroll
        for (int f = 0; f < 4; ++f)
            #pragma unroll
            for (int g = 0; g < 4; ++g)
                acc[f][g][0] = acc[f][g][1] = 0u;

        cur = nxt;
        Wt = Wn; Ot = On;
    }

    // ---- final reduction: once per CTA ---------------------------------------
    lsum = warp_sum(lsum);
    if (lane == 0) red[wid] = lsum;
    __syncthreads();
    if (wid == 0) {
        float v = (lane < 8) ? red[lane] : 0.f;
        v = warp_sum(v);
        if (lane == 0) {
            atomicAdd(&g_acc, (double)v);
            __threadfence();
            unsigned int t = atomicAdd(&g_ticket, 1u);
            if (t == NBLK - 1) {
                double total;
                asm volatile("ld.global.acquire.gpu.f64 %0, [%1];" : "=d"(total) : "l"(&g_acc));
                out[0] = (float)(total / ((double)N * (double)N));
                g_acc = 0.0;
                g_ticket = 0u;
                g_tile = NBLK;        // reset tile ticket for next graph replay
                __threadfence();
            }
        }
    }
}

extern "C" void kernel_launch(void* const* d_in, const int* in_sizes, int n_in,
                              void* d_out, int out_size) {
    const float* W = (const float*)d_in[0];
    const float* O = (const float*)d_in[1];
    float* out = (float*)d_out;

    cudaFuncSetAttribute(gemm_loss_mma, cudaFuncAttributeMaxDynamicSharedMemorySize, SM_TOTAL);

    row_stats_kernel<<<N / 4, 256>>>(W, O);
    gemm_loss_mma<<<NBLK, 256, SM_TOTAL>>>(out);
}

// round 14
// speedup vs baseline: 1.2566x; 1.2566x over previous
#include <cuda_runtime.h>
#include <cuda_fp16.h>
#include <cstdint>

#define N 4096
#define D 1024
#define EPSV 1e-8f
#define MARGIN 0.1f

#define BM 128
#define BN 128
#define BK 64          // 64 fp16 = 128 B per smem row (SW128 atom)
#define NKC (D / BK)   // 16 k-chunks
#define NCTAS ((N / BM) * (N / BN))   // 1024

// ---------------- device globals (scratch) -----------------------------------
__device__ float  g_rnw[N];
__device__ float  g_rno[N];
__device__ float  g_d[N];
__device__ double g_acc = 0.0;
__device__ unsigned int g_ticket = 0;
__device__ __half g_Wh[(size_t)N * D];
__device__ __half g_Oh[(size_t)N * D];

// ---------------- helpers ----------------------------------------------------
__device__ __forceinline__ uint32_t smem_u32(const void* p) {
    uint32_t a;
    asm("{ .reg .u64 t; cvta.to.shared.u64 t, %1; cvt.u32.u64 %0, t; }" : "=r"(a) : "l"(p));
    return a;
}
__device__ __forceinline__ float warp_sum(float v) {
    #pragma unroll
    for (int off = 16; off > 0; off >>= 1) v += __shfl_down_sync(0xFFFFFFFFu, v, off);
    return v;
}
__device__ __forceinline__ uint32_t swz128(uint32_t off) { return off ^ ((off >> 3) & 0x70); }

__device__ __forceinline__ void cp_async16(uint32_t saddr, const void* gaddr) {
    asm volatile("cp.async.cg.shared.global [%0], [%1], 16;" :: "r"(saddr), "l"(gaddr));
}
#define CP_COMMIT() asm volatile("cp.async.commit_group;" ::: "memory")
#define CP_WAIT0()  asm volatile("cp.async.wait_group 0;" ::: "memory")

__device__ __forceinline__ void ldsm_x4(uint32_t* r, uint32_t addr) {
    asm volatile("ldmatrix.sync.aligned.m8n8.x4.shared.b16 {%0,%1,%2,%3}, [%4];"
                 : "=r"(r[0]), "=r"(r[1]), "=r"(r[2]), "=r"(r[3]) : "r"(addr));
}
__device__ __forceinline__ void mma_f16acc(uint32_t* c, const uint32_t* a, const uint32_t* b) {
    asm volatile(
        "mma.sync.aligned.m16n8k16.row.col.f16.f16.f16.f16 "
        "{%0,%1}, {%2,%3,%4,%5}, {%6,%7}, {%0,%1};"
        : "+r"(c[0]), "+r"(c[1])
        : "r"(a[0]), "r"(a[1]), "r"(a[2]), "r"(a[3]), "r"(b[0]), "r"(b[1]));
}

// ---------------- kernel 1: row stats + fp16 convert (4 rows/block, MLP 8) ---
__global__ void row_stats_kernel(const float* __restrict__ W, const float* __restrict__ O) {
    const int t = threadIdx.x;
    const int r = t >> 6;
    const int c = t & 63;
    const int row = blockIdx.x * 4 + r;

    const float4* W4 = reinterpret_cast<const float4*>(W + (size_t)row * D);
    const float4* O4 = reinterpret_cast<const float4*>(O + (size_t)row * D);

    float4 a[4], b[4];
    #pragma unroll
    for (int i = 0; i < 4; ++i) a[i] = W4[c + 64 * i];
    #pragma unroll
    for (int i = 0; i < 4; ++i) b[i] = O4[c + 64 * i];

    uint2* Wp = reinterpret_cast<uint2*>(g_Wh + (size_t)row * D);
    uint2* Op = reinterpret_cast<uint2*>(g_Oh + (size_t)row * D);
    #pragma unroll
    for (int i = 0; i < 4; ++i) {
        __half2 lo = __float22half2_rn(make_float2(a[i].x, a[i].y));
        __half2 hi = __float22half2_rn(make_float2(a[i].z, a[i].w));
        Wp[c + 64 * i] = make_uint2(*(uint32_t*)&lo, *(uint32_t*)&hi);
    }
    #pragma unroll
    for (int i = 0; i < 4; ++i) {
        __half2 lo = __float22half2_rn(make_float2(b[i].x, b[i].y));
        __half2 hi = __float22half2_rn(make_float2(b[i].z, b[i].w));
        Op[c + 64 * i] = make_uint2(*(uint32_t*)&lo, *(uint32_t*)&hi);
    }

    float ww = 0.f, oo = 0.f, wo = 0.f;
    #pragma unroll
    for (int i = 0; i < 4; ++i) {
        ww += a[i].x*a[i].x + a[i].y*a[i].y + a[i].z*a[i].z + a[i].w*a[i].w;
        oo += b[i].x*b[i].x + b[i].y*b[i].y + b[i].z*b[i].z + b[i].w*b[i].w;
        wo += a[i].x*b[i].x + a[i].y*b[i].y + a[i].z*b[i].z + a[i].w*b[i].w;
    }
    ww = warp_sum(ww); oo = warp_sum(oo); wo = warp_sum(wo);

    __shared__ float sw[8], so[8], sd[8];
    const int lane = t & 31, wid = t >> 5;
    if (lane == 0) { sw[wid] = ww; so[wid] = oo; sd[wid] = wo; }
    __syncthreads();
    if (c == 0) {
        float vw = sw[2*r] + sw[2*r+1];
        float vo = so[2*r] + so[2*r+1];
        float vd = sd[2*r] + sd[2*r+1];
        float nw = sqrtf(vw), no = sqrtf(vo);
        float prod = fmaxf(nw * no, EPSV);
        g_rnw[row] = 1.0f / nw;
        g_rno[row] = 1.0f / no;
        g_d[row]   = vd / prod;
    }
}

// ---------------- kernel 2: fp16-acc mma GEMM, 2-stage, 1 barrier/chunk ------
// per CTA: 2x(A 16KB) + 2x(B 16KB) + stats ~= 67 KB -> 3 CTAs/SM
#define SM_A0    0
#define SM_A1    (SM_A0 + BM * 128)
#define SM_B0    (SM_A1 + BM * 128)
#define SM_B1    (SM_B0 + BN * 128)
#define SM_RNW   (SM_B1 + BN * 128)
#define SM_D     (SM_RNW + BM * 4)
#define SM_RNO   (SM_D  + BM * 4)
#define SM_TOTAL (SM_RNO + BN * 4)

__global__ __launch_bounds__(256, 3)
void gemm_loss_mma(float* __restrict__ out) {
    extern __shared__ char smem[];
    const uint32_t sbase = smem_u32(smem);
    const int tid  = threadIdx.x;
    const int wid  = tid >> 5;
    const int lane = tid & 31;
    const int bi = blockIdx.y;
    const int bj = blockIdx.x;
    const int warp_m = wid >> 2;       // 0..1 (64 rows each)
    const int warp_n = wid & 3;        // 0..3 (32 cols each)

    if (tid < 128) {
        reinterpret_cast<float*>(smem + SM_RNW)[tid] = g_rnw[bi * BM + tid];
        reinterpret_cast<float*>(smem + SM_D  )[tid] = g_d  [bi * BM + tid];
        reinterpret_cast<float*>(smem + SM_RNO)[tid] = g_rno[bj * BN + tid];
    }

    const __half* __restrict__ Wt = g_Wh + (size_t)(bi * BM) * D;
    const __half* __restrict__ Ot = g_Oh + (size_t)(bj * BN) * D;

    const int lrow = tid >> 3;
    const int lcol = tid & 7;

    uint32_t acc[4][4][2];
    #pragma unroll
    for (int f = 0; f < 4; ++f)
        #pragma unroll
        for (int g = 0; g < 4; ++g)
            acc[f][g][0] = acc[f][g][1] = 0u;

    const int a_row = warp_m * 64 + ((lane >> 3) & 1) * 8 + (lane & 7);
    const int a_cb  = (lane >> 4) * 16;
    const int b_row = warp_n * 32 + ((lane >> 4) & 1) * 8 + (lane & 7);
    const int b_cb  = ((lane >> 3) & 1) * 16;

    // prologue: load chunk 0 into buffer 0
    {
        #pragma unroll
        for (int i = 0; i < 4; ++i) {
            int row = lrow + i * 32;
            cp_async16(sbase + SM_A0 + swz128(row * 128 + lcol * 16),
                       Wt + (size_t)row * D + lcol * 8);
            cp_async16(sbase + SM_B0 + swz128(row * 128 + lcol * 16),
                       Ot + (size_t)row * D + lcol * 8);
        }
        CP_COMMIT();
    }

    #pragma unroll 1
    for (int kc = 0; kc < NKC; ++kc) {
        const int b = kc & 1;
        CP_WAIT0();
        // SINGLE barrier per chunk: it both publishes chunk kc's smem to all
        // warps AND proves every warp finished computing chunk kc-1 (program
        // order), so overwriting buffer b^1 below is safe without a trailing
        // barrier.
        __syncthreads();

        if (kc + 1 < NKC) {
            const int kt = (kc + 1) * BK;
            const uint32_t sa = sbase + (b ? SM_A0 : SM_A1);
            const uint32_t sb = sbase + (b ? SM_B0 : SM_B1);
            #pragma unroll
            for (int i = 0; i < 4; ++i) {
                int row = lrow + i * 32;
                cp_async16(sa + swz128(row * 128 + lcol * 16),
                           Wt + (size_t)row * D + kt + lcol * 8);
                cp_async16(sb + swz128(row * 128 + lcol * 16),
                           Ot + (size_t)row * D + kt + lcol * 8);
            }
            CP_COMMIT();
        }

        const uint32_t abuf = sbase + (b ? SM_A1 : SM_A0);
        const uint32_t bbuf = sbase + (b ? SM_B1 : SM_B0);

        #pragma unroll
        for (int ks = 0; ks < 4; ++ks) {
            uint32_t areg[4][4];
            uint32_t breg[2][4];
            #pragma unroll
            for (int f = 0; f < 4; ++f)
                ldsm_x4(areg[f], abuf + swz128((a_row + f * 16) * 128 + a_cb + ks * 32));
            #pragma unroll
            for (int nf2 = 0; nf2 < 2; ++nf2)
                ldsm_x4(breg[nf2], bbuf + swz128((b_row + nf2 * 16) * 128 + b_cb + ks * 32));
            #pragma unroll
            for (int f = 0; f < 4; ++f)
                #pragma unroll
                for (int g = 0; g < 4; ++g)
                    mma_f16acc(acc[f][g], areg[f], &breg[g >> 1][(g & 1) * 2]);
        }
        // no trailing barrier (see comment at top of loop)
    }

    // ---- fused epilogue (fp32 normalize, exact fp32 diagonal) ----------------
    const float* srnw = reinterpret_cast<const float*>(smem + SM_RNW);
    const float* sd   = reinterpret_cast<const float*>(smem + SM_D);
    const float* srno = reinterpret_cast<const float*>(smem + SM_RNO);

    const int qrow = lane >> 2;
    const int qcol = (lane & 3) * 2;

    float rno_v[8];
    #pragma unroll
    for (int g = 0; g < 4; ++g)
        #pragma unroll
        for (int e = 0; e < 2; ++e)
            rno_v[g * 2 + e] = srno[warp_n * 32 + g * 8 + qcol + e];

    float lsum = 0.f;
    #pragma unroll
    for (int f = 0; f < 4; ++f) {
        #pragma unroll
        for (int h = 0; h < 2; ++h) {
            const int rl = warp_m * 64 + f * 16 + qrow + h * 8;
            const int rg = bi * BM + rl;
            const float rnw_r = srnw[rl];
            const float d_r   = sd[rl];
            #pragma unroll
            for (int g = 0; g < 4; ++g) {
                const float2 sv = __half22float2(*reinterpret_cast<__half2*>(&acc[f][g][h]));
                #pragma unroll
                for (int e = 0; e < 2; ++e) {
                    const int cl = warp_n * 32 + g * 8 + qcol + e;
                    const int jg = bj * BN + cl;
                    const float S = (e ? sv.y : sv.x) * rnw_r * rno_v[g * 2 + e];
                    lsum += (rg == jg) ? (1.0f - d_r) : fmaxf(MARGIN - S + d_r, 0.0f);
                }
            }
        }
    }

    lsum = warp_sum(lsum);
    __shared__ float red[8];
    if (lane == 0) red[wid] = lsum;
    __syncthreads();
    if (wid == 0) {
        float v = (lane < 8) ? red[lane] : 0.f;
        v = warp_sum(v);
        if (lane == 0) {
            atomicAdd(&g_acc, (double)v);
            __threadfence();
            unsigned int t = atomicAdd(&g_ticket, 1u);
            if (t == NCTAS - 1) {
                double total;
                asm volatile("ld.global.acquire.gpu.f64 %0, [%1];" : "=d"(total) : "l"(&g_acc));
                out[0] = (float)(total / ((double)N * (double)N));
                g_acc = 0.0;
                g_ticket = 0u;
                __threadfence();
            }
        }
    }
}

extern "C" void kernel_launch(void* const* d_in, const int* in_sizes, int n_in,
                              void* d_out, int out_size) {
    const float* W = (const float*)d_in[0];
    const float* O = (const float*)d_in[1];
    float* out = (float*)d_out;

    cudaFuncSetAttribute(gemm_loss_mma, cudaFuncAttributeMaxDynamicSharedMemorySize, SM_TOTAL);

    row_stats_kernel<<<N / 4, 256>>>(W, O);

    dim3 grid(N / BN, N / BM);   // (32, 32)
    gemm_loss_mma<<<grid, 256, SM_TOTAL>>>(out);
}